// round 12
// baseline (speedup 1.0000x reference)
#include <cuda_runtime.h>
#include <math.h>
#include <stdint.h>

#define BATCH 8192
#define KOBJ  6
#define VD    2048
#define QD    1024
#define NH    1024
#define NROWS (BATCH*KOBJ)
#define LDW   (VD+QD)          // 3072, W1 row stride

// GEMM tiling: CTA 128x256x32, 16 warps (2m x 8n), warp tile 64x32
#define THREADS 512
#define BM 128
#define BN 256
#define BK 32
#define PAD 36                  // u32 pitch; row stride 144B (16B aligned for ldmatrix)
#define A_U32 (BM*PAD)
#define B_U32 (BN*PAD)
#define STG_U32 (A_U32+B_U32)
#define SMEM_DYN (2*STG_U32*4)  // 110592 B

__device__ float g_W1r[(size_t)NH*LDW];   // rna-rounded W1 (tf32 values in f32)
__device__ float g_P[(size_t)BATCH*NH];   // q-projection + b1
__device__ float g_logits[NROWS];

__device__ __forceinline__ uint32_t f2tf(float x){
    uint32_t r; asm("cvt.rna.tf32.f32 %0, %1;" : "=r"(r) : "f"(x)); return r;
}
__device__ __forceinline__ uint32_t smem_u32(const void* p){
    uint32_t a;
    asm("{ .reg .u64 t; cvta.to.shared.u64 t, %1; cvt.u32.u64 %0, t; }" : "=r"(a) : "l"(p));
    return a;
}
__device__ __forceinline__ void cp16(uint32_t dst, const void* src){
    asm volatile("cp.async.cg.shared.global [%0], [%1], 16;" :: "r"(dst), "l"(src) : "memory");
}
#define CP_COMMIT() asm volatile("cp.async.commit_group;" ::: "memory")
#define CP_WAIT(n)  asm volatile("cp.async.wait_group %0;" :: "n"(n) : "memory")

__device__ __forceinline__ void ldsm_x4(uint32_t &r0, uint32_t &r1, uint32_t &r2, uint32_t &r3,
                                        uint32_t addr){
    asm volatile("ldmatrix.sync.aligned.m8n8.x4.shared.b16 {%0,%1,%2,%3}, [%4];"
        : "=r"(r0), "=r"(r1), "=r"(r2), "=r"(r3) : "r"(addr));
}

__global__ void round_W1_kernel(const float* __restrict__ W1){
    size_t i = (size_t)blockIdx.x*blockDim.x + threadIdx.x;
    const float4 f = ((const float4*)W1)[i];
    ((uint4*)g_W1r)[i] = make_uint4(f2tf(f.x), f2tf(f.y), f2tf(f.z), f2tf(f.w));
}
__global__ void zero_logits_kernel(){
    int i = blockIdx.x*blockDim.x + threadIdx.x;
    if (i < NROWS) g_logits[i] = 0.f;
}

// C[m,n] = sum_k A[m,k]*W1r(n,k)
// EPI==0: A=q -> g_P[row,col] = C + bias
// EPI==1: A=v -> logits[row] += sum_col Wl[col]*relu(C + g_P[row/6,col])
template<int EPI>
__global__ void __launch_bounds__(THREADS, 1)
gemm_tc(const float* __restrict__ A,
        const float* __restrict__ bias, const float* __restrict__ Wl)
{
    constexpr int LDA  = (EPI == 0) ? QD : VD;
    constexpr int KDIM = (EPI == 0) ? QD : VD;
    constexpr int KOFF = (EPI == 0) ? VD : 0;
    constexpr int KT   = KDIM / BK;

    extern __shared__ uint32_t sm[];
    uint32_t* bufA[2] = { sm,          sm + STG_U32 };
    uint32_t* bufB[2] = { sm + A_U32,  sm + STG_U32 + A_U32 };

    const int tid  = threadIdx.x;
    const int warp = tid >> 5, lane = tid & 31;
    const int wm = warp & 1, wn = warp >> 1;      // 2m x 8n warp grid, warp tile 64x32
    const int grp = lane >> 2, tig = lane & 3;
    const int m0 = blockIdx.x * BM;
    const int n0 = blockIdx.y * BN;

    const float* Bw = g_W1r + KOFF;    // device-side symbol reference only

    // ldmatrix per-lane address components (u32-index units)
    const int aRow  = ((lane >> 3) & 1) * 8 + (lane & 7);
    const int aCol  = (lane >> 4) * 4;
    const int aIdx0 = (wm*64 + aRow) * PAD + aCol;        // + mi*16*PAD + kb
    const int bRow  = lane & 7;
    const int bNi   = ((lane >> 4) & 1) * 8;
    const int bCol  = ((lane >> 3) & 1) * 4;
    const int bIdx0 = (wn*32 + bNi + bRow) * PAD + bCol;  // + ni2*16*PAD + kb

    const uint32_t smA[2] = { smem_u32(bufA[0]), smem_u32(bufA[1]) };
    const uint32_t smB[2] = { smem_u32(bufB[0]), smem_u32(bufB[1]) };

    uint4 areg[2];   // A staged as already-rounded tf32 bits

    auto LDGA = [&](int t){
        #pragma unroll
        for (int j = 0; j < 2; j++){                       // 512 thr x 2 = 1024 float4 = 128x32
            int u = tid + THREADS*j, r = u >> 3, cc = u & 7;
            float4 f = __ldg((const float4*)(A + (size_t)(m0+r)*LDA + t*BK + cc*4));
            areg[j] = make_uint4(f2tf(f.x), f2tf(f.y), f2tf(f.z), f2tf(f.w));
        }
    };
    auto STSA = [&](int b){
        #pragma unroll
        for (int j = 0; j < 2; j++){
            int u = tid + THREADS*j, r = u >> 3, cc = u & 7;
            *(uint4*)(bufA[b] + r*PAD + cc*4) = areg[j];
        }
    };
    auto CPB = [&](int t, int b){
        #pragma unroll
        for (int j = 0; j < 4; j++){                       // 512 thr x 4 = 2048 float4 = 256x32
            int u = tid + THREADS*j, r = u >> 3, cc = u & 7;
            cp16(smem_u32(bufB[b] + r*PAD + cc*4),
                 Bw + (size_t)(n0+r)*LDW + t*BK + cc*4);
        }
        CP_COMMIT();
    };

    float c[4][4][4];
    #pragma unroll
    for (int i=0;i<4;i++)
      #pragma unroll
      for (int j=0;j<4;j++){ c[i][j][0]=0.f;c[i][j][1]=0.f;c[i][j][2]=0.f;c[i][j][3]=0.f; }

    // prologue: fill both stages (R6 proven structure)
    CPB(0,0); LDGA(0);
    CPB(1,1);
    STSA(0);
    LDGA(1);
    STSA(1);
    CP_WAIT(1);
    __syncthreads();

    for (int i = 0; i < KT; i++){
        if (i + 2 < KT) LDGA(i+2);

        const uint32_t sA = smA[i & 1];
        const uint32_t sB = smB[i & 1];
        #pragma unroll
        for (int ks = 0; ks < 4; ks++){
            const int kb = ks*8;
            uint32_t af[4][4], bfr[4][2];
            #pragma unroll
            for (int mi = 0; mi < 4; mi++)
                ldsm_x4(af[mi][0], af[mi][1], af[mi][2], af[mi][3],
                        sA + (uint32_t)(aIdx0 + mi*16*PAD + kb)*4u);
            #pragma unroll
            for (int ni2 = 0; ni2 < 2; ni2++)
                ldsm_x4(bfr[2*ni2][0], bfr[2*ni2][1], bfr[2*ni2+1][0], bfr[2*ni2+1][1],
                        sB + (uint32_t)(bIdx0 + ni2*16*PAD + kb)*4u);
            #pragma unroll
            for (int mi = 0; mi < 4; mi++)
              #pragma unroll
              for (int ni = 0; ni < 4; ni++)
                asm volatile("mma.sync.aligned.m16n8k8.row.col.f32.tf32.tf32.f32 "
                  "{%0,%1,%2,%3}, {%4,%5,%6,%7}, {%8,%9}, {%0,%1,%2,%3};"
                  : "+f"(c[mi][ni][0]), "+f"(c[mi][ni][1]),
                    "+f"(c[mi][ni][2]), "+f"(c[mi][ni][3])
                  : "r"(af[mi][0]), "r"(af[mi][1]), "r"(af[mi][2]), "r"(af[mi][3]),
                    "r"(bfr[ni][0]), "r"(bfr[ni][1]));
        }
        __syncthreads();
        if (i + 2 < KT){
            STSA(i & 1);
            CPB(i+2, i & 1);
            CP_WAIT(1);
        } else {
            CP_WAIT(0);
        }
        __syncthreads();
    }

    if (EPI == 0){
        #pragma unroll
        for (int ni = 0; ni < 4; ni++){
            int col = n0 + wn*32 + ni*8 + tig*2;
            float b0 = bias[col], b1v = bias[col+1];
            #pragma unroll
            for (int mi = 0; mi < 4; mi++){
                int row = m0 + wm*64 + mi*16 + grp;
                g_P[(size_t)row*NH + col    ] = c[mi][ni][0] + b0;
                g_P[(size_t)row*NH + col + 1] = c[mi][ni][1] + b1v;
                g_P[(size_t)(row+8)*NH + col    ] = c[mi][ni][2] + b0;
                g_P[(size_t)(row+8)*NH + col + 1] = c[mi][ni][3] + b1v;
            }
        }
    } else {
        #pragma unroll
        for (int mi = 0; mi < 4; mi++){
            int row = m0 + wm*64 + mi*16 + grp;
            int ba = row / KOBJ, bb = (row + 8) / KOBJ;
            float rs0 = 0.f, rs1 = 0.f;
            #pragma unroll
            for (int ni = 0; ni < 4; ni++){
                int col = n0 + wn*32 + ni*8 + tig*2;
                float wl0 = __ldg(Wl + col), wl1 = __ldg(Wl + col + 1);
                rs0 += fmaxf(c[mi][ni][0] + g_P[(size_t)ba*NH + col    ], 0.f) * wl0
                     + fmaxf(c[mi][ni][1] + g_P[(size_t)ba*NH + col + 1], 0.f) * wl1;
                rs1 += fmaxf(c[mi][ni][2] + g_P[(size_t)bb*NH + col    ], 0.f) * wl0
                     + fmaxf(c[mi][ni][3] + g_P[(size_t)bb*NH + col + 1], 0.f) * wl1;
            }
            rs0 += __shfl_xor_sync(0xffffffffu, rs0, 1);
            rs0 += __shfl_xor_sync(0xffffffffu, rs0, 2);
            rs1 += __shfl_xor_sync(0xffffffffu, rs1, 1);
            rs1 += __shfl_xor_sync(0xffffffffu, rs1, 2);
            if (tig == 0){
                atomicAdd(&g_logits[row],     rs0);
                atomicAdd(&g_logits[row + 8], rs1);
            }
        }
    }
}

__global__ void __launch_bounds__(256) final_kernel(
    const float* __restrict__ mask, const float* __restrict__ bl,
    const float* __restrict__ Wse1, const float* __restrict__ Wse2,
    const float* __restrict__ Wf,   const float* __restrict__ bf,
    float* __restrict__ out)
{
    int b = blockIdx.x, tid = threadIdx.x;
    __shared__ float  s_l[KOBJ], s_s[KOBJ];
    __shared__ float4 s_wf[VD/4], s_bf[VD/4];
    for (int d = tid; d < VD/4; d += 256){
        s_wf[d] = ((const float4*)Wf)[d];
        s_bf[d] = ((const float4*)bf)[d];
    }
    if (tid < KOBJ) s_l[tid] = g_logits[b*KOBJ + tid] + bl[0];
    __syncthreads();
    if (tid < KOBJ){
        float l = s_l[tid];
        float mx = s_l[0];
        #pragma unroll
        for (int k=1;k<KOBJ;k++) mx = fmaxf(mx, s_l[k]);
        float sum = 0.f;
        #pragma unroll
        for (int k=0;k<KOBJ;k++) sum += expf(s_l[k]-mx);
        out[b*KOBJ + tid] = expf(l-mx)/sum;
        float total = 0.f;
        #pragma unroll
        for (int k=0;k<KOBJ;k++) total += s_l[k]*mask[b*KOBJ+k];
        float x = total - l*mask[b*KOBJ+tid];
        float acc = 0.f;
        for (int i=0;i<128;i++) acc += Wse2[i]*fmaxf(x*Wse1[i], 0.f);
        float y = 1.f/(1.f + expf(-acc));
        s_s[tid] = x*(1.f-y) + l;
    }
    __syncthreads();
    float* out2 = out + NROWS;
    #pragma unroll
    for (int k=0;k<KOBJ;k++){
        float s = s_s[k];
        float4* o = (float4*)(out2 + (size_t)(b*KOBJ+k)*VD);
        for (int d = tid; d < VD/4; d += 256){
            float4 wf = s_wf[d], bv = s_bf[d];
            o[d] = make_float4(fmaf(s,wf.x,bv.x), fmaf(s,wf.y,bv.y),
                               fmaf(s,wf.z,bv.z), fmaf(s,wf.w,bv.w));
        }
    }
}

extern "C" void kernel_launch(void* const* d_in, const int* in_sizes, int n_in,
                              void* d_out, int out_size)
{
    const float* v    = (const float*)d_in[0];
    const float* q    = (const float*)d_in[1];
    const float* mask = (const float*)d_in[2];
    const float* W1   = (const float*)d_in[3];
    const float* b1   = (const float*)d_in[4];
    const float* Wl   = (const float*)d_in[5];
    const float* bl   = (const float*)d_in[6];
    const float* Wse1 = (const float*)d_in[7];
    const float* Wse2 = (const float*)d_in[8];
    const float* Wf   = (const float*)d_in[9];
    const float* bf   = (const float*)d_in[10];
    float* out = (float*)d_out;

    cudaFuncSetAttribute(gemm_tc<0>, cudaFuncAttributeMaxDynamicSharedMemorySize, SMEM_DYN);
    cudaFuncSetAttribute(gemm_tc<1>, cudaFuncAttributeMaxDynamicSharedMemorySize, SMEM_DYN);

    zero_logits_kernel<<<(NROWS+255)/256, 256>>>();
    round_W1_kernel<<<(NH*LDW/4)/256, 256>>>(W1);
    // Stage A: g_P[b,h] = q[b]·W1q[h] + b1[h]
    gemm_tc<0><<<dim3(BATCH/BM, NH/BN), THREADS, SMEM_DYN>>>(q, b1, nullptr);
    // Stage B: logits[row] += Σ_h Wl[h]·relu(v[row]·W1v[h] + g_P[row/6,h])
    gemm_tc<1><<<dim3(NROWS/BM, NH/BN), THREADS, SMEM_DYN>>>(v, nullptr, Wl);
    // Stage C
    final_kernel<<<BATCH, 256>>>(mask, bl, Wse1, Wse2, Wf, bf, out);
}

// round 13
// speedup vs baseline: 1.2755x; 1.2755x over previous
#include <cuda_runtime.h>
#include <math.h>
#include <stdint.h>

#define BATCH 8192
#define KOBJ  6
#define VD    2048
#define QD    1024
#define NH    1024
#define NROWS (BATCH*KOBJ)
#define LDW   (VD+QD)          // 3072, W1 row stride

// GEMM tiling: CTA 128x256x64, 8 warps (2m x 4n), warp tile 64x64
#define THREADS 256
#define BM 128
#define BN 256
#define BK 64
#define PAD 68                  // u32 pitch; row 272B (16B aligned; banks (4r+c)%32)
#define A_U32 (BM*PAD)
#define B_U32 (BN*PAD)
#define STG_U32 (A_U32+B_U32)
#define SMEM_DYN (2*STG_U32*4)  // 208896 B

__device__ float g_W1r[(size_t)NH*LDW];   // rna-rounded W1 (tf32 values in f32)
__device__ float g_P[(size_t)BATCH*NH];   // q-projection + b1
__device__ float g_logits[NROWS];

__device__ __forceinline__ uint32_t f2tf(float x){
    uint32_t r; asm("cvt.rna.tf32.f32 %0, %1;" : "=r"(r) : "f"(x)); return r;
}
__device__ __forceinline__ uint32_t smem_u32(const void* p){
    uint32_t a;
    asm("{ .reg .u64 t; cvta.to.shared.u64 t, %1; cvt.u32.u64 %0, t; }" : "=r"(a) : "l"(p));
    return a;
}
__device__ __forceinline__ void cp16(uint32_t dst, const void* src){
    asm volatile("cp.async.cg.shared.global [%0], [%1], 16;" :: "r"(dst), "l"(src) : "memory");
}
#define CP_COMMIT() asm volatile("cp.async.commit_group;" ::: "memory")
#define CP_WAIT(n)  asm volatile("cp.async.wait_group %0;" :: "n"(n) : "memory")

__device__ __forceinline__ void ldsm_x4(uint32_t &r0, uint32_t &r1, uint32_t &r2, uint32_t &r3,
                                        uint32_t addr){
    asm volatile("ldmatrix.sync.aligned.m8n8.x4.shared.b16 {%0,%1,%2,%3}, [%4];"
        : "=r"(r0), "=r"(r1), "=r"(r2), "=r"(r3) : "r"(addr));
}

__global__ void round_W1_kernel(const float* __restrict__ W1){
    size_t i = (size_t)blockIdx.x*blockDim.x + threadIdx.x;
    const float4 f = ((const float4*)W1)[i];
    ((uint4*)g_W1r)[i] = make_uint4(f2tf(f.x), f2tf(f.y), f2tf(f.z), f2tf(f.w));
}
__global__ void zero_logits_kernel(){
    int i = blockIdx.x*blockDim.x + threadIdx.x;
    if (i < NROWS) g_logits[i] = 0.f;
}

// C[m,n] = sum_k A[m,k]*W1r(n,k)   (A fed raw fp32 -> tf32 truncation; W1 pre-rounded)
// EPI==0: A=q -> g_P[row,col] = C + bias
// EPI==1: A=v -> logits[row] += sum_col Wl[col]*relu(C + g_P[row/6,col])
template<int EPI>
__global__ void __launch_bounds__(THREADS, 1)
gemm_tc(const float* __restrict__ A,
        const float* __restrict__ bias, const float* __restrict__ Wl)
{
    constexpr int LDA  = (EPI == 0) ? QD : VD;
    constexpr int KDIM = (EPI == 0) ? QD : VD;
    constexpr int KOFF = (EPI == 0) ? VD : 0;
    constexpr int KT   = KDIM / BK;      // 32 (stage B), 16 (stage A)

    extern __shared__ uint32_t sm[];
    uint32_t* bufA[2] = { sm,          sm + STG_U32 };
    uint32_t* bufB[2] = { sm + A_U32,  sm + STG_U32 + A_U32 };

    const int tid  = threadIdx.x;
    const int warp = tid >> 5, lane = tid & 31;
    const int wm = warp & 1, wn = warp >> 1;      // 2m x 4n warp grid
    const int grp = lane >> 2, tig = lane & 3;
    const int m0 = blockIdx.x * BM;
    const int n0 = blockIdx.y * BN;

    const float* Bw = g_W1r + KOFF;    // device-side symbol reference only

    // ldmatrix per-lane address components (u32-index units)
    const int aRow  = ((lane >> 3) & 1) * 8 + (lane & 7);
    const int aCol  = (lane >> 4) * 4;
    const int aIdx0 = (wm*64 + aRow) * PAD + aCol;        // + mi*16*PAD + kb
    const int bRow  = lane & 7;
    const int bNi   = ((lane >> 4) & 1) * 8;
    const int bCol  = ((lane >> 3) & 1) * 4;
    const int bIdx0 = (wn*64 + bNi + bRow) * PAD + bCol;  // + ni2*16*PAD + kb

    const uint32_t smA[2] = { smem_u32(bufA[0]), smem_u32(bufA[1]) };
    const uint32_t smB[2] = { smem_u32(bufB[0]), smem_u32(bufB[1]) };

    // both tiles stream via cp.async; one commit group per k-tile
    auto CPAB = [&](int t, int b){
        #pragma unroll
        for (int j = 0; j < 8; j++){                       // A: 128 rows x 16 chunks
            int u = tid + THREADS*j, r = u >> 4, cc = u & 15;
            cp16(smem_u32(bufA[b] + r*PAD + cc*4),
                 A + (size_t)(m0+r)*LDA + t*BK + cc*4);
        }
        #pragma unroll
        for (int j = 0; j < 16; j++){                      // B: 256 rows x 16 chunks
            int u = tid + THREADS*j, r = u >> 4, cc = u & 15;
            cp16(smem_u32(bufB[b] + r*PAD + cc*4),
                 Bw + (size_t)(n0+r)*LDW + t*BK + cc*4);
        }
        CP_COMMIT();
    };

    float c[4][8][4];
    #pragma unroll
    for (int i=0;i<4;i++)
      #pragma unroll
      for (int j=0;j<8;j++){ c[i][j][0]=0.f;c[i][j][1]=0.f;c[i][j][2]=0.f;c[i][j][3]=0.f; }

    // prologue: both stages in flight
    CPAB(0,0);
    CPAB(1,1);
    CP_WAIT(1);
    __syncthreads();

    for (int i = 0; i < KT; i++){
        const uint32_t sA = smA[i & 1];
        const uint32_t sB = smB[i & 1];
        #pragma unroll
        for (int ks = 0; ks < BK/8; ks++){
            const int kb = ks*8;
            uint32_t af[4][4], bfr[8][2];
            #pragma unroll
            for (int mi = 0; mi < 4; mi++)
                ldsm_x4(af[mi][0], af[mi][1], af[mi][2], af[mi][3],
                        sA + (uint32_t)(aIdx0 + mi*16*PAD + kb)*4u);
            #pragma unroll
            for (int ni2 = 0; ni2 < 4; ni2++)
                ldsm_x4(bfr[2*ni2][0], bfr[2*ni2][1], bfr[2*ni2+1][0], bfr[2*ni2+1][1],
                        sB + (uint32_t)(bIdx0 + ni2*16*PAD + kb)*4u);
            #pragma unroll
            for (int mi = 0; mi < 4; mi++)
              #pragma unroll
              for (int ni = 0; ni < 8; ni++)
                asm volatile("mma.sync.aligned.m16n8k8.row.col.f32.tf32.tf32.f32 "
                  "{%0,%1,%2,%3}, {%4,%5,%6,%7}, {%8,%9}, {%0,%1,%2,%3};"
                  : "+f"(c[mi][ni][0]), "+f"(c[mi][ni][1]),
                    "+f"(c[mi][ni][2]), "+f"(c[mi][ni][3])
                  : "r"(af[mi][0]), "r"(af[mi][1]), "r"(af[mi][2]), "r"(af[mi][3]),
                    "r"(bfr[ni][0]), "r"(bfr[ni][1]));
        }
        __syncthreads();
        if (i + 2 < KT){
            CPAB(i+2, i & 1);
            CP_WAIT(1);
        } else {
            CP_WAIT(0);
        }
        __syncthreads();
    }

    if (EPI == 0){
        #pragma unroll
        for (int ni = 0; ni < 8; ni++){
            int col = n0 + wn*64 + ni*8 + tig*2;
            float b0 = bias[col], b1v = bias[col+1];
            #pragma unroll
            for (int mi = 0; mi < 4; mi++){
                int row = m0 + wm*64 + mi*16 + grp;
                g_P[(size_t)row*NH + col    ] = c[mi][ni][0] + b0;
                g_P[(size_t)row*NH + col + 1] = c[mi][ni][1] + b1v;
                g_P[(size_t)(row+8)*NH + col    ] = c[mi][ni][2] + b0;
                g_P[(size_t)(row+8)*NH + col + 1] = c[mi][ni][3] + b1v;
            }
        }
    } else {
        #pragma unroll
        for (int mi = 0; mi < 4; mi++){
            int row = m0 + wm*64 + mi*16 + grp;
            int ba = row / KOBJ, bb = (row + 8) / KOBJ;
            float rs0 = 0.f, rs1 = 0.f;
            #pragma unroll
            for (int ni = 0; ni < 8; ni++){
                int col = n0 + wn*64 + ni*8 + tig*2;
                float wl0 = __ldg(Wl + col), wl1 = __ldg(Wl + col + 1);
                rs0 += fmaxf(c[mi][ni][0] + g_P[(size_t)ba*NH + col    ], 0.f) * wl0
                     + fmaxf(c[mi][ni][1] + g_P[(size_t)ba*NH + col + 1], 0.f) * wl1;
                rs1 += fmaxf(c[mi][ni][2] + g_P[(size_t)bb*NH + col    ], 0.f) * wl0
                     + fmaxf(c[mi][ni][3] + g_P[(size_t)bb*NH + col + 1], 0.f) * wl1;
            }
            rs0 += __shfl_xor_sync(0xffffffffu, rs0, 1);
            rs0 += __shfl_xor_sync(0xffffffffu, rs0, 2);
            rs1 += __shfl_xor_sync(0xffffffffu, rs1, 1);
            rs1 += __shfl_xor_sync(0xffffffffu, rs1, 2);
            if (tig == 0){
                atomicAdd(&g_logits[row],     rs0);
                atomicAdd(&g_logits[row + 8], rs1);
            }
        }
    }
}

__global__ void __launch_bounds__(256) final_kernel(
    const float* __restrict__ mask, const float* __restrict__ bl,
    const float* __restrict__ Wse1, const float* __restrict__ Wse2,
    const float* __restrict__ Wf,   const float* __restrict__ bf,
    float* __restrict__ out)
{
    int b = blockIdx.x, tid = threadIdx.x;
    __shared__ float  s_l[KOBJ], s_s[KOBJ];
    __shared__ float4 s_wf[VD/4], s_bf[VD/4];
    for (int d = tid; d < VD/4; d += 256){
        s_wf[d] = ((const float4*)Wf)[d];
        s_bf[d] = ((const float4*)bf)[d];
    }
    if (tid < KOBJ) s_l[tid] = g_logits[b*KOBJ + tid] + bl[0];
    __syncthreads();
    if (tid < KOBJ){
        float l = s_l[tid];
        float mx = s_l[0];
        #pragma unroll
        for (int k=1;k<KOBJ;k++) mx = fmaxf(mx, s_l[k]);
        float sum = 0.f;
        #pragma unroll
        for (int k=0;k<KOBJ;k++) sum += expf(s_l[k]-mx);
        out[b*KOBJ + tid] = expf(l-mx)/sum;
        float total = 0.f;
        #pragma unroll
        for (int k=0;k<KOBJ;k++) total += s_l[k]*mask[b*KOBJ+k];
        float x = total - l*mask[b*KOBJ+tid];
        float acc = 0.f;
        for (int i=0;i<128;i++) acc += Wse2[i]*fmaxf(x*Wse1[i], 0.f);
        float y = 1.f/(1.f + expf(-acc));
        s_s[tid] = x*(1.f-y) + l;
    }
    __syncthreads();
    float* out2 = out + NROWS;
    #pragma unroll
    for (int k=0;k<KOBJ;k++){
        float s = s_s[k];
        float4* o = (float4*)(out2 + (size_t)(b*KOBJ+k)*VD);
        for (int d = tid; d < VD/4; d += 256){
            float4 wf = s_wf[d], bv = s_bf[d];
            o[d] = make_float4(fmaf(s,wf.x,bv.x), fmaf(s,wf.y,bv.y),
                               fmaf(s,wf.z,bv.z), fmaf(s,wf.w,bv.w));
        }
    }
}

extern "C" void kernel_launch(void* const* d_in, const int* in_sizes, int n_in,
                              void* d_out, int out_size)
{
    const float* v    = (const float*)d_in[0];
    const float* q    = (const float*)d_in[1];
    const float* mask = (const float*)d_in[2];
    const float* W1   = (const float*)d_in[3];
    const float* b1   = (const float*)d_in[4];
    const float* Wl   = (const float*)d_in[5];
    const float* bl   = (const float*)d_in[6];
    const float* Wse1 = (const float*)d_in[7];
    const float* Wse2 = (const float*)d_in[8];
    const float* Wf   = (const float*)d_in[9];
    const float* bf   = (const float*)d_in[10];
    float* out = (float*)d_out;

    cudaFuncSetAttribute(gemm_tc<0>, cudaFuncAttributeMaxDynamicSharedMemorySize, SMEM_DYN);
    cudaFuncSetAttribute(gemm_tc<1>, cudaFuncAttributeMaxDynamicSharedMemorySize, SMEM_DYN);

    zero_logits_kernel<<<(NROWS+255)/256, 256>>>();
    round_W1_kernel<<<(NH*LDW/4)/256, 256>>>(W1);
    // Stage A: g_P[b,h] = q[b]·W1q[h] + b1[h]
    gemm_tc<0><<<dim3(BATCH/BM, NH/BN), THREADS, SMEM_DYN>>>(q, b1, nullptr);
    // Stage B: logits[row] += Σ_h Wl[h]·relu(v[row]·W1v[h] + g_P[row/6,h])
    gemm_tc<1><<<dim3(NROWS/BM, NH/BN), THREADS, SMEM_DYN>>>(v, nullptr, Wl);
    // Stage C
    final_kernel<<<BATCH, 256>>>(mask, bl, Wse1, Wse2, Wf, bf, out);
}

// round 14
// speedup vs baseline: 1.3615x; 1.0675x over previous
#include <cuda_runtime.h>
#include <math.h>
#include <stdint.h>

#define BATCH 8192
#define KOBJ  6
#define VD    2048
#define QD    1024
#define NH    1024
#define NROWS (BATCH*KOBJ)
#define LDW   (VD+QD)          // 3072, W1 row stride

// GEMM tiling: CTA 128x128x32, 8 warps (2m x 4n), warp tile 64x32, 2 CTAs/SM
#define THREADS 256
#define BM 128
#define BN 128
#define BK 32
#define PAD 36                  // u32 pitch; row 144B
#define A_U32 (BM*PAD)
#define B_U32 (BN*PAD)
#define STG_U32 (A_U32+B_U32)
#define SMEM_DYN (2*STG_U32*4)  // 73728 B per CTA -> 2 CTAs/SM

__device__ float g_W1r[(size_t)NH*LDW];   // rna-rounded W1 (tf32 values in f32)
__device__ float g_P[(size_t)BATCH*NH];   // q-projection + b1
__device__ float g_logits[NROWS];

__device__ __forceinline__ uint32_t f2tf(float x){
    uint32_t r; asm("cvt.rna.tf32.f32 %0, %1;" : "=r"(r) : "f"(x)); return r;
}
__device__ __forceinline__ uint32_t smem_u32(const void* p){
    uint32_t a;
    asm("{ .reg .u64 t; cvta.to.shared.u64 t, %1; cvt.u32.u64 %0, t; }" : "=r"(a) : "l"(p));
    return a;
}
__device__ __forceinline__ void cp16(uint32_t dst, const void* src){
    asm volatile("cp.async.cg.shared.global [%0], [%1], 16;" :: "r"(dst), "l"(src) : "memory");
}
#define CP_COMMIT() asm volatile("cp.async.commit_group;" ::: "memory")
#define CP_WAIT(n)  asm volatile("cp.async.wait_group %0;" :: "n"(n) : "memory")

__device__ __forceinline__ void ldsm_x4(uint32_t &r0, uint32_t &r1, uint32_t &r2, uint32_t &r3,
                                        uint32_t addr){
    asm volatile("ldmatrix.sync.aligned.m8n8.x4.shared.b16 {%0,%1,%2,%3}, [%4];"
        : "=r"(r0), "=r"(r1), "=r"(r2), "=r"(r3) : "r"(addr));
}

__global__ void round_W1_kernel(const float* __restrict__ W1){
    size_t i = (size_t)blockIdx.x*blockDim.x + threadIdx.x;
    const float4 f = ((const float4*)W1)[i];
    ((uint4*)g_W1r)[i] = make_uint4(f2tf(f.x), f2tf(f.y), f2tf(f.z), f2tf(f.w));
}
__global__ void zero_logits_kernel(){
    int i = blockIdx.x*blockDim.x + threadIdx.x;
    if (i < NROWS) g_logits[i] = 0.f;
}

// C[m,n] = sum_k A[m,k]*W1r(n,k)   (A raw fp32 -> tf32 truncation; W1 pre-rounded)
// EPI==0: A=q -> g_P[row,col] = C + bias
// EPI==1: A=v -> logits[row] += sum_col Wl[col]*relu(C + g_P[row/6,col])
template<int EPI>
__global__ void __launch_bounds__(THREADS, 2)
gemm_tc(const float* __restrict__ A,
        const float* __restrict__ bias, const float* __restrict__ Wl)
{
    constexpr int LDA  = (EPI == 0) ? QD : VD;
    constexpr int KDIM = (EPI == 0) ? QD : VD;
    constexpr int KOFF = (EPI == 0) ? VD : 0;
    constexpr int KT   = KDIM / BK;      // 64 (stage B), 32 (stage A)

    extern __shared__ uint32_t sm[];
    uint32_t* bufA[2] = { sm,          sm + STG_U32 };
    uint32_t* bufB[2] = { sm + A_U32,  sm + STG_U32 + A_U32 };

    const int tid  = threadIdx.x;
    const int warp = tid >> 5, lane = tid & 31;
    const int wm = warp & 1, wn = warp >> 1;      // 2m x 4n warp grid, warp tile 64x32
    const int grp = lane >> 2, tig = lane & 3;
    const int m0 = blockIdx.x * BM;
    const int n0 = blockIdx.y * BN;

    const float* Bw = g_W1r + KOFF;    // device-side symbol reference only

    // ldmatrix per-lane address components (u32-index units)
    const int aRow  = ((lane >> 3) & 1) * 8 + (lane & 7);
    const int aCol  = (lane >> 4) * 4;
    const int aIdx0 = (wm*64 + aRow) * PAD + aCol;        // + mi*16*PAD + kb
    const int bRow  = lane & 7;
    const int bNi   = ((lane >> 4) & 1) * 8;
    const int bCol  = ((lane >> 3) & 1) * 4;
    const int bIdx0 = (wn*32 + bNi + bRow) * PAD + bCol;  // + ni2*16*PAD + kb

    const uint32_t smA[2] = { smem_u32(bufA[0]), smem_u32(bufA[1]) };
    const uint32_t smB[2] = { smem_u32(bufB[0]), smem_u32(bufB[1]) };

    // both tiles via cp.async; one commit group per k-tile
    auto CPAB = [&](int t, int b){
        #pragma unroll
        for (int j = 0; j < 4; j++){                       // A: 128 rows x 8 chunks
            int u = tid + THREADS*j, r = u >> 3, cc = u & 7;
            cp16(smem_u32(bufA[b] + r*PAD + cc*4),
                 A + (size_t)(m0+r)*LDA + t*BK + cc*4);
        }
        #pragma unroll
        for (int j = 0; j < 4; j++){                       // B: 128 rows x 8 chunks
            int u = tid + THREADS*j, r = u >> 3, cc = u & 7;
            cp16(smem_u32(bufB[b] + r*PAD + cc*4),
                 Bw + (size_t)(n0+r)*LDW + t*BK + cc*4);
        }
        CP_COMMIT();
    };

    float c[4][4][4];
    #pragma unroll
    for (int i=0;i<4;i++)
      #pragma unroll
      for (int j=0;j<4;j++){ c[i][j][0]=0.f;c[i][j][1]=0.f;c[i][j][2]=0.f;c[i][j][3]=0.f; }

    // prologue: both stages in flight
    CPAB(0,0);
    CPAB(1,1);
    CP_WAIT(1);
    __syncthreads();

    for (int i = 0; i < KT; i++){
        const uint32_t sA = smA[i & 1];
        const uint32_t sB = smB[i & 1];
        #pragma unroll
        for (int ks = 0; ks < BK/8; ks++){
            const int kb = ks*8;
            uint32_t af[4][4], bfr[4][2];
            #pragma unroll
            for (int mi = 0; mi < 4; mi++)
                ldsm_x4(af[mi][0], af[mi][1], af[mi][2], af[mi][3],
                        sA + (uint32_t)(aIdx0 + mi*16*PAD + kb)*4u);
            #pragma unroll
            for (int ni2 = 0; ni2 < 2; ni2++)
                ldsm_x4(bfr[2*ni2][0], bfr[2*ni2][1], bfr[2*ni2+1][0], bfr[2*ni2+1][1],
                        sB + (uint32_t)(bIdx0 + ni2*16*PAD + kb)*4u);
            #pragma unroll
            for (int mi = 0; mi < 4; mi++)
              #pragma unroll
              for (int ni = 0; ni < 4; ni++)
                asm volatile("mma.sync.aligned.m16n8k8.row.col.f32.tf32.tf32.f32 "
                  "{%0,%1,%2,%3}, {%4,%5,%6,%7}, {%8,%9}, {%0,%1,%2,%3};"
                  : "+f"(c[mi][ni][0]), "+f"(c[mi][ni][1]),
                    "+f"(c[mi][ni][2]), "+f"(c[mi][ni][3])
                  : "r"(af[mi][0]), "r"(af[mi][1]), "r"(af[mi][2]), "r"(af[mi][3]),
                    "r"(bfr[ni][0]), "r"(bfr[ni][1]));
        }
        __syncthreads();
        if (i + 2 < KT){
            CPAB(i+2, i & 1);
            CP_WAIT(1);
        } else {
            CP_WAIT(0);
        }
        __syncthreads();
    }

    if (EPI == 0){
        #pragma unroll
        for (int ni = 0; ni < 4; ni++){
            int col = n0 + wn*32 + ni*8 + tig*2;
            float b0 = bias[col], b1v = bias[col+1];
            #pragma unroll
            for (int mi = 0; mi < 4; mi++){
                int row = m0 + wm*64 + mi*16 + grp;
                g_P[(size_t)row*NH + col    ] = c[mi][ni][0] + b0;
                g_P[(size_t)row*NH + col + 1] = c[mi][ni][1] + b1v;
                g_P[(size_t)(row+8)*NH + col    ] = c[mi][ni][2] + b0;
                g_P[(size_t)(row+8)*NH + col + 1] = c[mi][ni][3] + b1v;
            }
        }
    } else {
        #pragma unroll
        for (int mi = 0; mi < 4; mi++){
            int row = m0 + wm*64 + mi*16 + grp;
            int ba = row / KOBJ, bb = (row + 8) / KOBJ;
            float rs0 = 0.f, rs1 = 0.f;
            #pragma unroll
            for (int ni = 0; ni < 4; ni++){
                int col = n0 + wn*32 + ni*8 + tig*2;
                float wl0 = __ldg(Wl + col), wl1 = __ldg(Wl + col + 1);
                rs0 += fmaxf(c[mi][ni][0] + g_P[(size_t)ba*NH + col    ], 0.f) * wl0
                     + fmaxf(c[mi][ni][1] + g_P[(size_t)ba*NH + col + 1], 0.f) * wl1;
                rs1 += fmaxf(c[mi][ni][2] + g_P[(size_t)bb*NH + col    ], 0.f) * wl0
                     + fmaxf(c[mi][ni][3] + g_P[(size_t)bb*NH + col + 1], 0.f) * wl1;
            }
            rs0 += __shfl_xor_sync(0xffffffffu, rs0, 1);
            rs0 += __shfl_xor_sync(0xffffffffu, rs0, 2);
            rs1 += __shfl_xor_sync(0xffffffffu, rs1, 1);
            rs1 += __shfl_xor_sync(0xffffffffu, rs1, 2);
            if (tig == 0){
                atomicAdd(&g_logits[row],     rs0);
                atomicAdd(&g_logits[row + 8], rs1);
            }
        }
    }
}

__global__ void __launch_bounds__(256) final_kernel(
    const float* __restrict__ mask, const float* __restrict__ bl,
    const float* __restrict__ Wse1, const float* __restrict__ Wse2,
    const float* __restrict__ Wf,   const float* __restrict__ bf,
    float* __restrict__ out)
{
    int b = blockIdx.x, tid = threadIdx.x;
    __shared__ float  s_l[KOBJ], s_s[KOBJ];
    __shared__ float4 s_wf[VD/4], s_bf[VD/4];
    for (int d = tid; d < VD/4; d += 256){
        s_wf[d] = ((const float4*)Wf)[d];
        s_bf[d] = ((const float4*)bf)[d];
    }
    if (tid < KOBJ) s_l[tid] = g_logits[b*KOBJ + tid] + bl[0];
    __syncthreads();
    if (tid < KOBJ){
        float l = s_l[tid];
        float mx = s_l[0];
        #pragma unroll
        for (int k=1;k<KOBJ;k++) mx = fmaxf(mx, s_l[k]);
        float sum = 0.f;
        #pragma unroll
        for (int k=0;k<KOBJ;k++) sum += expf(s_l[k]-mx);
        out[b*KOBJ + tid] = expf(l-mx)/sum;
        float total = 0.f;
        #pragma unroll
        for (int k=0;k<KOBJ;k++) total += s_l[k]*mask[b*KOBJ+k];
        float x = total - l*mask[b*KOBJ+tid];
        float acc = 0.f;
        for (int i=0;i<128;i++) acc += Wse2[i]*fmaxf(x*Wse1[i], 0.f);
        float y = 1.f/(1.f + expf(-acc));
        s_s[tid] = x*(1.f-y) + l;
    }
    __syncthreads();
    float* out2 = out + NROWS;
    #pragma unroll
    for (int k=0;k<KOBJ;k++){
        float s = s_s[k];
        float4* o = (float4*)(out2 + (size_t)(b*KOBJ+k)*VD);
        for (int d = tid; d < VD/4; d += 256){
            float4 wf = s_wf[d], bv = s_bf[d];
            o[d] = make_float4(fmaf(s,wf.x,bv.x), fmaf(s,wf.y,bv.y),
                               fmaf(s,wf.z,bv.z), fmaf(s,wf.w,bv.w));
        }
    }
}

extern "C" void kernel_launch(void* const* d_in, const int* in_sizes, int n_in,
                              void* d_out, int out_size)
{
    const float* v    = (const float*)d_in[0];
    const float* q    = (const float*)d_in[1];
    const float* mask = (const float*)d_in[2];
    const float* W1   = (const float*)d_in[3];
    const float* b1   = (const float*)d_in[4];
    const float* Wl   = (const float*)d_in[5];
    const float* bl   = (const float*)d_in[6];
    const float* Wse1 = (const float*)d_in[7];
    const float* Wse2 = (const float*)d_in[8];
    const float* Wf   = (const float*)d_in[9];
    const float* bf   = (const float*)d_in[10];
    float* out = (float*)d_out;

    cudaFuncSetAttribute(gemm_tc<0>, cudaFuncAttributeMaxDynamicSharedMemorySize, SMEM_DYN);
    cudaFuncSetAttribute(gemm_tc<1>, cudaFuncAttributeMaxDynamicSharedMemorySize, SMEM_DYN);

    zero_logits_kernel<<<(NROWS+255)/256, 256>>>();
    round_W1_kernel<<<(NH*LDW/4)/256, 256>>>(W1);
    // Stage A: g_P[b,h] = q[b]·W1q[h] + b1[h]
    gemm_tc<0><<<dim3(BATCH/BM, NH/BN), THREADS, SMEM_DYN>>>(q, b1, nullptr);
    // Stage B: logits[row] += Σ_h Wl[h]·relu(v[row]·W1v[h] + g_P[row/6,h])
    gemm_tc<1><<<dim3(NROWS/BM, NH/BN), THREADS, SMEM_DYN>>>(v, nullptr, Wl);
    // Stage C
    final_kernel<<<BATCH, 256>>>(mask, bl, Wse1, Wse2, Wf, bf, out);
}

// round 15
// speedup vs baseline: 1.3938x; 1.0237x over previous
#include <cuda_runtime.h>
#include <math.h>
#include <stdint.h>

#define BATCH 8192
#define KOBJ  6
#define VD    2048
#define QD    1024
#define NH    1024
#define NROWS (BATCH*KOBJ)
#define LDW   (VD+QD)          // 3072, W1 row stride

// GEMM tiling: CTA 128x128x32, 8 warps (2m x 4n), warp tile 64x32, 2 CTAs/SM
// 3-stage cp.async ring, ONE barrier per k-tile
#define THREADS 256
#define BM 128
#define BN 128
#define BK 32
#define PAD 36                  // u32 pitch; row 144B
#define A_U32 (BM*PAD)
#define B_U32 (BN*PAD)
#define STG_U32 (A_U32+B_U32)
#define NSTAGE 3
#define SMEM_DYN (NSTAGE*STG_U32*4)  // 110592 B per CTA -> 2 CTAs/SM (221184 B)

__device__ float g_W1r[(size_t)NH*LDW];   // rna-rounded W1 (tf32 values in f32)
__device__ float g_P[(size_t)BATCH*NH];   // q-projection + b1
__device__ float g_logits[NROWS];

__device__ __forceinline__ uint32_t f2tf(float x){
    uint32_t r; asm("cvt.rna.tf32.f32 %0, %1;" : "=r"(r) : "f"(x)); return r;
}
__device__ __forceinline__ uint32_t smem_u32(const void* p){
    uint32_t a;
    asm("{ .reg .u64 t; cvta.to.shared.u64 t, %1; cvt.u32.u64 %0, t; }" : "=r"(a) : "l"(p));
    return a;
}
__device__ __forceinline__ void cp16(uint32_t dst, const void* src){
    asm volatile("cp.async.cg.shared.global [%0], [%1], 16;" :: "r"(dst), "l"(src) : "memory");
}
#define CP_COMMIT() asm volatile("cp.async.commit_group;" ::: "memory")
#define CP_WAIT(n)  asm volatile("cp.async.wait_group %0;" :: "n"(n) : "memory")

__device__ __forceinline__ void ldsm_x4(uint32_t &r0, uint32_t &r1, uint32_t &r2, uint32_t &r3,
                                        uint32_t addr){
    asm volatile("ldmatrix.sync.aligned.m8n8.x4.shared.b16 {%0,%1,%2,%3}, [%4];"
        : "=r"(r0), "=r"(r1), "=r"(r2), "=r"(r3) : "r"(addr));
}

__global__ void round_W1_kernel(const float* __restrict__ W1){
    size_t i = (size_t)blockIdx.x*blockDim.x + threadIdx.x;
    const float4 f = ((const float4*)W1)[i];
    ((uint4*)g_W1r)[i] = make_uint4(f2tf(f.x), f2tf(f.y), f2tf(f.z), f2tf(f.w));
}
__global__ void zero_logits_kernel(){
    int i = blockIdx.x*blockDim.x + threadIdx.x;
    if (i < NROWS) g_logits[i] = 0.f;
}

// C[m,n] = sum_k A[m,k]*W1r(n,k)   (A raw fp32 -> tf32 truncation; W1 pre-rounded)
// EPI==0: A=q -> g_P[row,col] = C + bias
// EPI==1: A=v -> logits[row] += sum_col Wl[col]*relu(C + g_P[row/6,col])
template<int EPI>
__global__ void __launch_bounds__(THREADS, 2)
gemm_tc(const float* __restrict__ A,
        const float* __restrict__ bias, const float* __restrict__ Wl)
{
    constexpr int LDA  = (EPI == 0) ? QD : VD;
    constexpr int KDIM = (EPI == 0) ? QD : VD;
    constexpr int KOFF = (EPI == 0) ? VD : 0;
    constexpr int KT   = KDIM / BK;      // 64 (stage B), 32 (stage A)

    extern __shared__ uint32_t sm[];

    const int tid  = threadIdx.x;
    const int warp = tid >> 5, lane = tid & 31;
    const int wm = warp & 1, wn = warp >> 1;      // 2m x 4n warp grid, warp tile 64x32
    const int grp = lane >> 2, tig = lane & 3;
    const int m0 = blockIdx.x * BM;
    const int n0 = blockIdx.y * BN;

    const float* Bw = g_W1r + KOFF;    // device-side symbol reference only

    // ldmatrix per-lane address components (u32-index units)
    const int aRow  = ((lane >> 3) & 1) * 8 + (lane & 7);
    const int aCol  = (lane >> 4) * 4;
    const int aIdx0 = (wm*64 + aRow) * PAD + aCol;        // + mi*16*PAD + kb
    const int bRow  = lane & 7;
    const int bNi   = ((lane >> 4) & 1) * 8;
    const int bCol  = ((lane >> 3) & 1) * 4;
    const int bIdx0 = (wn*32 + bNi + bRow) * PAD + bCol;  // + ni2*16*PAD + kb

    const uint32_t smBase = smem_u32(sm);

    // both tiles via cp.async; one commit group per k-tile
    auto CPAB = [&](int t, int slot){
        uint32_t* bufA = sm + slot*STG_U32;
        uint32_t* bufB = bufA + A_U32;
        #pragma unroll
        for (int j = 0; j < 4; j++){                       // A: 128 rows x 8 chunks
            int u = tid + THREADS*j, r = u >> 3, cc = u & 7;
            cp16(smem_u32(bufA + r*PAD + cc*4),
                 A + (size_t)(m0+r)*LDA + t*BK + cc*4);
        }
        #pragma unroll
        for (int j = 0; j < 4; j++){                       // B: 128 rows x 8 chunks
            int u = tid + THREADS*j, r = u >> 3, cc = u & 7;
            cp16(smem_u32(bufB + r*PAD + cc*4),
                 Bw + (size_t)(n0+r)*LDW + t*BK + cc*4);
        }
        CP_COMMIT();
    };

    float c[4][4][4];
    #pragma unroll
    for (int i=0;i<4;i++)
      #pragma unroll
      for (int j=0;j<4;j++){ c[i][j][0]=0.f;c[i][j][1]=0.f;c[i][j][2]=0.f;c[i][j][3]=0.f; }

    // prologue: tiles 0,1 staged
    CPAB(0, 0);
    CPAB(1, 1);
    CP_WAIT(1);          // tile 0 resident
    __syncthreads();

    int sw = 2, sr = 0;  // write slot = (i+2)%3, read slot = i%3
    for (int i = 0; i < KT; i++){
        if (i + 2 < KT) CPAB(i+2, sw);   // lands during this tile's compute

        const uint32_t sA = smBase + (uint32_t)(sr*STG_U32)*4u;
        const uint32_t sB = sA + (uint32_t)A_U32*4u;
        #pragma unroll
        for (int ks = 0; ks < BK/8; ks++){
            const int kb = ks*8;
            uint32_t af[4][4], bfr[4][2];
            #pragma unroll
            for (int mi = 0; mi < 4; mi++)
                ldsm_x4(af[mi][0], af[mi][1], af[mi][2], af[mi][3],
                        sA + (uint32_t)(aIdx0 + mi*16*PAD + kb)*4u);
            #pragma unroll
            for (int ni2 = 0; ni2 < 2; ni2++)
                ldsm_x4(bfr[2*ni2][0], bfr[2*ni2][1], bfr[2*ni2+1][0], bfr[2*ni2+1][1],
                        sB + (uint32_t)(bIdx0 + ni2*16*PAD + kb)*4u);
            #pragma unroll
            for (int mi = 0; mi < 4; mi++)
              #pragma unroll
              for (int ni = 0; ni < 4; ni++)
                asm volatile("mma.sync.aligned.m16n8k8.row.col.f32.tf32.tf32.f32 "
                  "{%0,%1,%2,%3}, {%4,%5,%6,%7}, {%8,%9}, {%0,%1,%2,%3};"
                  : "+f"(c[mi][ni][0]), "+f"(c[mi][ni][1]),
                    "+f"(c[mi][ni][2]), "+f"(c[mi][ni][3])
                  : "r"(af[mi][0]), "r"(af[mi][1]), "r"(af[mi][2]), "r"(af[mi][3]),
                    "r"(bfr[ni][0]), "r"(bfr[ni][1]));
        }
        // single synchronization point per k-tile
        if (i + 2 < KT){ CP_WAIT(1); } else { CP_WAIT(0); }
        __syncthreads();

        sw = (sw == 2) ? 0 : sw + 1;
        sr = (sr == 2) ? 0 : sr + 1;
    }

    if (EPI == 0){
        #pragma unroll
        for (int ni = 0; ni < 4; ni++){
            int col = n0 + wn*32 + ni*8 + tig*2;
            float b0 = bias[col], b1v = bias[col+1];
            #pragma unroll
            for (int mi = 0; mi < 4; mi++){
                int row = m0 + wm*64 + mi*16 + grp;
                g_P[(size_t)row*NH + col    ] = c[mi][ni][0] + b0;
                g_P[(size_t)row*NH + col + 1] = c[mi][ni][1] + b1v;
                g_P[(size_t)(row+8)*NH + col    ] = c[mi][ni][2] + b0;
                g_P[(size_t)(row+8)*NH + col + 1] = c[mi][ni][3] + b1v;
            }
        }
    } else {
        #pragma unroll
        for (int mi = 0; mi < 4; mi++){
            int row = m0 + wm*64 + mi*16 + grp;
            int ba = row / KOBJ, bb = (row + 8) / KOBJ;
            float rs0 = 0.f, rs1 = 0.f;
            #pragma unroll
            for (int ni = 0; ni < 4; ni++){
                int col = n0 + wn*32 + ni*8 + tig*2;
                float wl0 = __ldg(Wl + col), wl1 = __ldg(Wl + col + 1);
                rs0 += fmaxf(c[mi][ni][0] + g_P[(size_t)ba*NH + col    ], 0.f) * wl0
                     + fmaxf(c[mi][ni][1] + g_P[(size_t)ba*NH + col + 1], 0.f) * wl1;
                rs1 += fmaxf(c[mi][ni][2] + g_P[(size_t)bb*NH + col    ], 0.f) * wl0
                     + fmaxf(c[mi][ni][3] + g_P[(size_t)bb*NH + col + 1], 0.f) * wl1;
            }
            rs0 += __shfl_xor_sync(0xffffffffu, rs0, 1);
            rs0 += __shfl_xor_sync(0xffffffffu, rs0, 2);
            rs1 += __shfl_xor_sync(0xffffffffu, rs1, 1);
            rs1 += __shfl_xor_sync(0xffffffffu, rs1, 2);
            if (tig == 0){
                atomicAdd(&g_logits[row],     rs0);
                atomicAdd(&g_logits[row + 8], rs1);
            }
        }
    }
}

__global__ void __launch_bounds__(256) final_kernel(
    const float* __restrict__ mask, const float* __restrict__ bl,
    const float* __restrict__ Wse1, const float* __restrict__ Wse2,
    const float* __restrict__ Wf,   const float* __restrict__ bf,
    float* __restrict__ out)
{
    int b = blockIdx.x, tid = threadIdx.x;
    __shared__ float  s_l[KOBJ], s_s[KOBJ];
    __shared__ float4 s_wf[VD/4], s_bf[VD/4];
    for (int d = tid; d < VD/4; d += 256){
        s_wf[d] = ((const float4*)Wf)[d];
        s_bf[d] = ((const float4*)bf)[d];
    }
    if (tid < KOBJ) s_l[tid] = g_logits[b*KOBJ + tid] + bl[0];
    __syncthreads();
    if (tid < KOBJ){
        float l = s_l[tid];
        float mx = s_l[0];
        #pragma unroll
        for (int k=1;k<KOBJ;k++) mx = fmaxf(mx, s_l[k]);
        float sum = 0.f;
        #pragma unroll
        for (int k=0;k<KOBJ;k++) sum += expf(s_l[k]-mx);
        out[b*KOBJ + tid] = expf(l-mx)/sum;
        float total = 0.f;
        #pragma unroll
        for (int k=0;k<KOBJ;k++) total += s_l[k]*mask[b*KOBJ+k];
        float x = total - l*mask[b*KOBJ+tid];
        float acc = 0.f;
        for (int i=0;i<128;i++) acc += Wse2[i]*fmaxf(x*Wse1[i], 0.f);
        float y = 1.f/(1.f + expf(-acc));
        s_s[tid] = x*(1.f-y) + l;
    }
    __syncthreads();
    float* out2 = out + NROWS;
    #pragma unroll
    for (int k=0;k<KOBJ;k++){
        float s = s_s[k];
        float4* o = (float4*)(out2 + (size_t)(b*KOBJ+k)*VD);
        for (int d = tid; d < VD/4; d += 256){
            float4 wf = s_wf[d], bv = s_bf[d];
            o[d] = make_float4(fmaf(s,wf.x,bv.x), fmaf(s,wf.y,bv.y),
                               fmaf(s,wf.z,bv.z), fmaf(s,wf.w,bv.w));
        }
    }
}

extern "C" void kernel_launch(void* const* d_in, const int* in_sizes, int n_in,
                              void* d_out, int out_size)
{
    const float* v    = (const float*)d_in[0];
    const float* q    = (const float*)d_in[1];
    const float* mask = (const float*)d_in[2];
    const float* W1   = (const float*)d_in[3];
    const float* b1   = (const float*)d_in[4];
    const float* Wl   = (const float*)d_in[5];
    const float* bl   = (const float*)d_in[6];
    const float* Wse1 = (const float*)d_in[7];
    const float* Wse2 = (const float*)d_in[8];
    const float* Wf   = (const float*)d_in[9];
    const float* bf   = (const float*)d_in[10];
    float* out = (float*)d_out;

    cudaFuncSetAttribute(gemm_tc<0>, cudaFuncAttributeMaxDynamicSharedMemorySize, SMEM_DYN);
    cudaFuncSetAttribute(gemm_tc<1>, cudaFuncAttributeMaxDynamicSharedMemorySize, SMEM_DYN);

    zero_logits_kernel<<<(NROWS+255)/256, 256>>>();
    round_W1_kernel<<<(NH*LDW/4)/256, 256>>>(W1);
    // Stage A: g_P[b,h] = q[b]·W1q[h] + b1[h]
    gemm_tc<0><<<dim3(BATCH/BM, NH/BN), THREADS, SMEM_DYN>>>(q, b1, nullptr);
    // Stage B: logits[row] += Σ_h Wl[h]·relu(v[row]·W1v[h] + g_P[row/6,h])
    gemm_tc<1><<<dim3(NROWS/BM, NH/BN), THREADS, SMEM_DYN>>>(v, nullptr, Wl);
    // Stage C
    final_kernel<<<BATCH, 256>>>(mask, bl, Wse1, Wse2, Wf, bf, out);
}

// round 16
// speedup vs baseline: 1.4426x; 1.0351x over previous
#include <cuda_runtime.h>
#include <math.h>
#include <stdint.h>

#define BATCH 8192
#define KOBJ  6
#define VD    2048
#define QD    1024
#define NH    1024
#define NROWS (BATCH*KOBJ)
#define LDW   (VD+QD)          // 3072, W1 row stride

// GEMM tiling: CTA 128x128x32, 8 warps (2m x 4n), warp tile 64x32, 2 CTAs/SM
// 3-stage cp.async ring, ONE barrier per k-tile (R15 proven)
#define THREADS 256
#define BM 128
#define BN 128
#define BK 32
#define PAD 36                  // u32 pitch; row 144B
#define A_U32 (BM*PAD)
#define B_U32 (BN*PAD)
#define STG_U32 (A_U32+B_U32)
#define NSTAGE 3
#define SMEM_DYN (NSTAGE*STG_U32*4)  // 110592 B per CTA -> 2 CTAs/SM

#define NBLK_A 512              // stage-A blocks (64 m-tiles x 8 n-tiles)
#define NBLK_B 3072             // stage-B blocks (384 x 8)

__device__ float g_W1r[(size_t)NH*LDW];   // rna-rounded W1 (tf32 values in f32)
__device__ float g_P[(size_t)BATCH*NH];   // q-projection + b1
__device__ float g_logits[NROWS];
__device__ int   g_done;                  // stage-A completion counter

__device__ __forceinline__ uint32_t f2tf(float x){
    uint32_t r; asm("cvt.rna.tf32.f32 %0, %1;" : "=r"(r) : "f"(x)); return r;
}
__device__ __forceinline__ uint32_t smem_u32(const void* p){
    uint32_t a;
    asm("{ .reg .u64 t; cvta.to.shared.u64 t, %1; cvt.u32.u64 %0, t; }" : "=r"(a) : "l"(p));
    return a;
}
__device__ __forceinline__ void cp16(uint32_t dst, const void* src){
    asm volatile("cp.async.cg.shared.global [%0], [%1], 16;" :: "r"(dst), "l"(src) : "memory");
}
#define CP_COMMIT() asm volatile("cp.async.commit_group;" ::: "memory")
#define CP_WAIT(n)  asm volatile("cp.async.wait_group %0;" :: "n"(n) : "memory")

__device__ __forceinline__ void ldsm_x4(uint32_t &r0, uint32_t &r1, uint32_t &r2, uint32_t &r3,
                                        uint32_t addr){
    asm volatile("ldmatrix.sync.aligned.m8n8.x4.shared.b16 {%0,%1,%2,%3}, [%4];"
        : "=r"(r0), "=r"(r1), "=r"(r2), "=r"(r3) : "r"(addr));
}

__global__ void round_W1_kernel(const float* __restrict__ W1){
    size_t i = (size_t)blockIdx.x*blockDim.x + threadIdx.x;
    const float4 f = ((const float4*)W1)[i];
    ((uint4*)g_W1r)[i] = make_uint4(f2tf(f.x), f2tf(f.y), f2tf(f.z), f2tf(f.w));
}
__global__ void zero_logits_kernel(){
    int i = blockIdx.x*blockDim.x + threadIdx.x;
    if (i < NROWS) g_logits[i] = 0.f;
    if (i == 0) g_done = 0;
}

// C[m,n] = sum_k A[m,k]*W1r(n,k)   (A raw fp32 -> tf32 truncation; W1 pre-rounded)
// EPI==0: A=q -> g_P[row,col] = C + bias; bump g_done
// EPI==1: A=v -> spin until g_done==NBLK_A, then logits += sum Wl*relu(C + g_P)
template<int EPI>
__device__ __forceinline__ void gemm_body(
    int m0, int n0,
    const float* __restrict__ A,
    const float* __restrict__ bias, const float* __restrict__ Wl,
    uint32_t* sm)
{
    constexpr int LDA  = (EPI == 0) ? QD : VD;
    constexpr int KDIM = (EPI == 0) ? QD : VD;
    constexpr int KOFF = (EPI == 0) ? VD : 0;
    constexpr int KT   = KDIM / BK;

    const int tid  = threadIdx.x;
    const int warp = tid >> 5, lane = tid & 31;
    const int wm = warp & 1, wn = warp >> 1;
    const int grp = lane >> 2, tig = lane & 3;

    const float* Bw = g_W1r + KOFF;

    const int aRow  = ((lane >> 3) & 1) * 8 + (lane & 7);
    const int aCol  = (lane >> 4) * 4;
    const int aIdx0 = (wm*64 + aRow) * PAD + aCol;
    const int bRow  = lane & 7;
    const int bNi   = ((lane >> 4) & 1) * 8;
    const int bCol  = ((lane >> 3) & 1) * 4;
    const int bIdx0 = (wn*32 + bNi + bRow) * PAD + bCol;

    const uint32_t smBase = smem_u32(sm);

    auto CPAB = [&](int t, int slot){
        uint32_t* bufA = sm + slot*STG_U32;
        uint32_t* bufB = bufA + A_U32;
        #pragma unroll
        for (int j = 0; j < 4; j++){
            int u = tid + THREADS*j, r = u >> 3, cc = u & 7;
            cp16(smem_u32(bufA + r*PAD + cc*4),
                 A + (size_t)(m0+r)*LDA + t*BK + cc*4);
        }
        #pragma unroll
        for (int j = 0; j < 4; j++){
            int u = tid + THREADS*j, r = u >> 3, cc = u & 7;
            cp16(smem_u32(bufB + r*PAD + cc*4),
                 Bw + (size_t)(n0+r)*LDW + t*BK + cc*4);
        }
        CP_COMMIT();
    };

    float c[4][4][4];
    #pragma unroll
    for (int i=0;i<4;i++)
      #pragma unroll
      for (int j=0;j<4;j++){ c[i][j][0]=0.f;c[i][j][1]=0.f;c[i][j][2]=0.f;c[i][j][3]=0.f; }

    CPAB(0, 0);
    CPAB(1, 1);
    CP_WAIT(1);
    __syncthreads();

    int sw = 2, sr = 0;
    for (int i = 0; i < KT; i++){
        if (i + 2 < KT) CPAB(i+2, sw);

        const uint32_t sA = smBase + (uint32_t)(sr*STG_U32)*4u;
        const uint32_t sB = sA + (uint32_t)A_U32*4u;
        #pragma unroll
        for (int ks = 0; ks < BK/8; ks++){
            const int kb = ks*8;
            uint32_t af[4][4], bfr[4][2];
            #pragma unroll
            for (int mi = 0; mi < 4; mi++)
                ldsm_x4(af[mi][0], af[mi][1], af[mi][2], af[mi][3],
                        sA + (uint32_t)(aIdx0 + mi*16*PAD + kb)*4u);
            #pragma unroll
            for (int ni2 = 0; ni2 < 2; ni2++)
                ldsm_x4(bfr[2*ni2][0], bfr[2*ni2][1], bfr[2*ni2+1][0], bfr[2*ni2+1][1],
                        sB + (uint32_t)(bIdx0 + ni2*16*PAD + kb)*4u);
            #pragma unroll
            for (int mi = 0; mi < 4; mi++)
              #pragma unroll
              for (int ni = 0; ni < 4; ni++)
                asm volatile("mma.sync.aligned.m16n8k8.row.col.f32.tf32.tf32.f32 "
                  "{%0,%1,%2,%3}, {%4,%5,%6,%7}, {%8,%9}, {%0,%1,%2,%3};"
                  : "+f"(c[mi][ni][0]), "+f"(c[mi][ni][1]),
                    "+f"(c[mi][ni][2]), "+f"(c[mi][ni][3])
                  : "r"(af[mi][0]), "r"(af[mi][1]), "r"(af[mi][2]), "r"(af[mi][3]),
                    "r"(bfr[ni][0]), "r"(bfr[ni][1]));
        }
        if (i + 2 < KT){ CP_WAIT(1); } else { CP_WAIT(0); }
        __syncthreads();

        sw = (sw == 2) ? 0 : sw + 1;
        sr = (sr == 2) ? 0 : sr + 1;
    }

    if (EPI == 0){
        #pragma unroll
        for (int ni = 0; ni < 4; ni++){
            int col = n0 + wn*32 + ni*8 + tig*2;
            float b0 = bias[col], b1v = bias[col+1];
            #pragma unroll
            for (int mi = 0; mi < 4; mi++){
                int row = m0 + wm*64 + mi*16 + grp;
                g_P[(size_t)row*NH + col    ] = c[mi][ni][0] + b0;
                g_P[(size_t)row*NH + col + 1] = c[mi][ni][1] + b1v;
                g_P[(size_t)(row+8)*NH + col    ] = c[mi][ni][2] + b0;
                g_P[(size_t)(row+8)*NH + col + 1] = c[mi][ni][3] + b1v;
            }
        }
        // publish: all block stores done -> fence -> count
        __syncthreads();
        if (tid == 0){
            __threadfence();
            atomicAdd(&g_done, 1);
        }
    } else {
        // wait for all stage-A blocks (in practice already done: A = wave-1 bids)
        if (tid == 0){
            while (*((volatile int*)&g_done) < NBLK_A) __nanosleep(64);
        }
        __syncthreads();
        __threadfence();
        #pragma unroll
        for (int mi = 0; mi < 4; mi++){
            int row = m0 + wm*64 + mi*16 + grp;
            int ba = row / KOBJ, bb = (row + 8) / KOBJ;
            float rs0 = 0.f, rs1 = 0.f;
            #pragma unroll
            for (int ni = 0; ni < 4; ni++){
                int col = n0 + wn*32 + ni*8 + tig*2;
                float wl0 = __ldg(Wl + col), wl1 = __ldg(Wl + col + 1);
                rs0 += fmaxf(c[mi][ni][0] + g_P[(size_t)ba*NH + col    ], 0.f) * wl0
                     + fmaxf(c[mi][ni][1] + g_P[(size_t)ba*NH + col + 1], 0.f) * wl1;
                rs1 += fmaxf(c[mi][ni][2] + g_P[(size_t)bb*NH + col    ], 0.f) * wl0
                     + fmaxf(c[mi][ni][3] + g_P[(size_t)bb*NH + col + 1], 0.f) * wl1;
            }
            rs0 += __shfl_xor_sync(0xffffffffu, rs0, 1);
            rs0 += __shfl_xor_sync(0xffffffffu, rs0, 2);
            rs1 += __shfl_xor_sync(0xffffffffu, rs1, 1);
            rs1 += __shfl_xor_sync(0xffffffffu, rs1, 2);
            if (tig == 0){
                atomicAdd(&g_logits[row],     rs0);
                atomicAdd(&g_logits[row + 8], rs1);
            }
        }
    }
}

// one launch: bids [0,512) = stage A (wave-1, retire fast), rest = stage B
__global__ void __launch_bounds__(THREADS, 2)
gemm_merged(const float* __restrict__ v, const float* __restrict__ q,
            const float* __restrict__ b1, const float* __restrict__ Wl)
{
    extern __shared__ uint32_t sm[];
    const int bid = blockIdx.x;
    if (bid < NBLK_A){
        gemm_body<0>((bid & 63)*BM, (bid >> 6)*BN, q, b1, nullptr, sm);
    } else {
        const int b = bid - NBLK_A;
        gemm_body<1>((b % 384)*BM, (b / 384)*BN, v, nullptr, Wl, sm);
    }
}

__global__ void __launch_bounds__(256) final_kernel(
    const float* __restrict__ mask, const float* __restrict__ bl,
    const float* __restrict__ Wse1, const float* __restrict__ Wse2,
    const float* __restrict__ Wf,   const float* __restrict__ bf,
    float* __restrict__ out)
{
    int b = blockIdx.x, tid = threadIdx.x;
    __shared__ float  s_l[KOBJ], s_s[KOBJ];
    __shared__ float4 s_wf[VD/4], s_bf[VD/4];
    for (int d = tid; d < VD/4; d += 256){
        s_wf[d] = ((const float4*)Wf)[d];
        s_bf[d] = ((const float4*)bf)[d];
    }
    if (tid < KOBJ) s_l[tid] = g_logits[b*KOBJ + tid] + bl[0];
    __syncthreads();
    if (tid < KOBJ){
        float l = s_l[tid];
        float mx = s_l[0];
        #pragma unroll
        for (int k=1;k<KOBJ;k++) mx = fmaxf(mx, s_l[k]);
        float sum = 0.f;
        #pragma unroll
        for (int k=0;k<KOBJ;k++) sum += expf(s_l[k]-mx);
        out[b*KOBJ + tid] = expf(l-mx)/sum;
        float total = 0.f;
        #pragma unroll
        for (int k=0;k<KOBJ;k++) total += s_l[k]*mask[b*KOBJ+k];
        float x = total - l*mask[b*KOBJ+tid];
        float acc = 0.f;
        for (int i=0;i<128;i++) acc += Wse2[i]*fmaxf(x*Wse1[i], 0.f);
        float y = 1.f/(1.f + expf(-acc));
        s_s[tid] = x*(1.f-y) + l;
    }
    __syncthreads();
    float* out2 = out + NROWS;
    #pragma unroll
    for (int k=0;k<KOBJ;k++){
        float s = s_s[k];
        float4* o = (float4*)(out2 + (size_t)(b*KOBJ+k)*VD);
        for (int d = tid; d < VD/4; d += 256){
            float4 wf = s_wf[d], bv = s_bf[d];
            __stcs(o + d, make_float4(fmaf(s,wf.x,bv.x), fmaf(s,wf.y,bv.y),
                                      fmaf(s,wf.z,bv.z), fmaf(s,wf.w,bv.w)));
        }
    }
}

extern "C" void kernel_launch(void* const* d_in, const int* in_sizes, int n_in,
                              void* d_out, int out_size)
{
    const float* v    = (const float*)d_in[0];
    const float* q    = (const float*)d_in[1];
    const float* mask = (const float*)d_in[2];
    const float* W1   = (const float*)d_in[3];
    const float* b1   = (const float*)d_in[4];
    const float* Wl   = (const float*)d_in[5];
    const float* bl   = (const float*)d_in[6];
    const float* Wse1 = (const float*)d_in[7];
    const float* Wse2 = (const float*)d_in[8];
    const float* Wf   = (const float*)d_in[9];
    const float* bf   = (const float*)d_in[10];
    float* out = (float*)d_out;

    cudaFuncSetAttribute(gemm_merged, cudaFuncAttributeMaxDynamicSharedMemorySize, SMEM_DYN);

    zero_logits_kernel<<<(NROWS+255)/256, 256>>>();
    round_W1_kernel<<<(NH*LDW/4)/256, 256>>>(W1);
    gemm_merged<<<NBLK_A + NBLK_B, THREADS, SMEM_DYN>>>(v, q, b1, Wl);
    final_kernel<<<BATCH, 256>>>(mask, bl, Wse1, Wse2, Wf, bf, out);
}

// round 17
// speedup vs baseline: 2.1064x; 1.4601x over previous
#include <cuda_runtime.h>
#include <cuda_fp16.h>
#include <math.h>
#include <stdint.h>

#define BATCH 8192
#define KOBJ  6
#define VD    2048
#define QD    1024
#define NH    1024
#define NROWS (BATCH*KOBJ)
#define LDW   (VD+QD)          // 3072, W1 row stride

// GEMM tiling: CTA 128x128x32(fp16), 8 warps (2m x 4n), warp tile 64x32, 2 CTAs/SM
// 3-stage cp.async ring, ONE barrier per k-tile (R15/R16 proven structure)
#define THREADS 256
#define BM 128
#define BN 128
#define BK 32                   // k elements per tile
#define PADH 40                 // half pitch; row = 80B (16B aligned, ldsm conflict-free)
#define A_H (BM*PADH)
#define B_H (BN*PADH)
#define STG_H (A_H+B_H)         // 10240 halfs = 20480B
#define NSTAGE 3
#define SMEM_DYN (NSTAGE*STG_H*2)   // 61440B per CTA -> 2 CTAs/SM

#define NBLK_A 512              // stage-A blocks (64 m-tiles x 8 n-tiles)
#define NBLK_B 3072             // stage-B blocks (384 x 8)

__device__ __half g_W1h[(size_t)NH*LDW];   // rn-rounded W1 (fp16)
__device__ __half g_vh[(size_t)NROWS*VD];  // fp16 v
__device__ __half g_qh[(size_t)BATCH*QD];  // fp16 q
__device__ float  g_P[(size_t)BATCH*NH];   // q-projection + b1
__device__ float  g_logits[NROWS];
__device__ int    g_done;                  // stage-A completion counter

__device__ __forceinline__ uint32_t smem_u32(const void* p){
    uint32_t a;
    asm("{ .reg .u64 t; cvta.to.shared.u64 t, %1; cvt.u32.u64 %0, t; }" : "=r"(a) : "l"(p));
    return a;
}
__device__ __forceinline__ void cp16(uint32_t dst, const void* src){
    asm volatile("cp.async.cg.shared.global [%0], [%1], 16;" :: "r"(dst), "l"(src) : "memory");
}
#define CP_COMMIT() asm volatile("cp.async.commit_group;" ::: "memory")
#define CP_WAIT(n)  asm volatile("cp.async.wait_group %0;" :: "n"(n) : "memory")

__device__ __forceinline__ void ldsm_x4(uint32_t &r0, uint32_t &r1, uint32_t &r2, uint32_t &r3,
                                        uint32_t addr){
    asm volatile("ldmatrix.sync.aligned.m8n8.x4.shared.b16 {%0,%1,%2,%3}, [%4];"
        : "=r"(r0), "=r"(r1), "=r"(r2), "=r"(r3) : "r"(addr));
}

// ---- fp16 conversion prepasses (device-symbol outputs referenced in device code) ----
__global__ void cvt_v_kernel(const float4* __restrict__ s){
    size_t i = (size_t)blockIdx.x*blockDim.x + threadIdx.x;
    float4 f = s[i];
    __half2* d = (__half2*)g_vh;
    d[2*i  ] = __floats2half2_rn(f.x, f.y);
    d[2*i+1] = __floats2half2_rn(f.z, f.w);
}
__global__ void cvt_q_kernel(const float4* __restrict__ s){
    size_t i = (size_t)blockIdx.x*blockDim.x + threadIdx.x;
    float4 f = s[i];
    __half2* d = (__half2*)g_qh;
    d[2*i  ] = __floats2half2_rn(f.x, f.y);
    d[2*i+1] = __floats2half2_rn(f.z, f.w);
}
__global__ void cvt_w_kernel(const float4* __restrict__ s){
    size_t i = (size_t)blockIdx.x*blockDim.x + threadIdx.x;
    float4 f = s[i];
    __half2* d = (__half2*)g_W1h;
    d[2*i  ] = __floats2half2_rn(f.x, f.y);
    d[2*i+1] = __floats2half2_rn(f.z, f.w);
}
__global__ void zero_logits_kernel(){
    int i = blockIdx.x*blockDim.x + threadIdx.x;
    if (i < NROWS) g_logits[i] = 0.f;
    if (i == 0) g_done = 0;
}

// C[m,n] = sum_k A[m,k]*W1h(n,k)  (all fp16 operands, fp32 accumulate)
// EPI==0: A=qh -> g_P[row,col] = C + bias; bump g_done
// EPI==1: A=vh -> spin until g_done==NBLK_A, then logits += sum Wl*relu(C + g_P)
template<int EPI>
__device__ __forceinline__ void gemm_body(
    int m0, int n0,
    const __half* __restrict__ Ah,
    const float* __restrict__ bias, const float* __restrict__ Wl,
    __half* sm)
{
    constexpr int LDA  = (EPI == 0) ? QD : VD;
    constexpr int KDIM = (EPI == 0) ? QD : VD;
    constexpr int KOFF = (EPI == 0) ? VD : 0;
    constexpr int KT   = KDIM / BK;      // 64 (stage B), 32 (stage A)

    const int tid  = threadIdx.x;
    const int warp = tid >> 5, lane = tid & 31;
    const int wm = warp & 1, wn = warp >> 1;      // 2m x 4n warp grid, warp tile 64x32
    const int grp = lane >> 2, tig = lane & 3;

    const __half* Bw = g_W1h + KOFF;

    // ldmatrix per-lane BYTE offsets within tiles
    const int aRow   = ((lane >> 3) & 1) * 8 + (lane & 7);
    const int aIdx0B = (wm*64 + aRow) * 80 + (lane >> 4) * 16;      // + mi*16*80 + ks*32
    const int bRow   = lane & 7;
    const int bNi    = ((lane >> 4) & 1) * 8;
    const int bIdx0B = (wn*32 + bNi + bRow) * 80 + ((lane >> 3) & 1) * 16;  // + ni2*16*80 + ks*32

    const uint32_t smBase = smem_u32(sm);

    auto CPAB = [&](int t, int slot){
        __half* bufA = sm + slot*STG_H;
        __half* bufB = bufA + A_H;
        #pragma unroll
        for (int j = 0; j < 2; j++){                 // A: 128 rows x 4 chunks(16B)
            int u = tid + THREADS*j, r = u >> 2, cc = u & 3;
            cp16(smem_u32(bufA + r*PADH + cc*8),
                 Ah + (size_t)(m0+r)*LDA + t*BK + cc*8);
        }
        #pragma unroll
        for (int j = 0; j < 2; j++){                 // B: 128 rows x 4 chunks(16B)
            int u = tid + THREADS*j, r = u >> 2, cc = u & 3;
            cp16(smem_u32(bufB + r*PADH + cc*8),
                 Bw + (size_t)(n0+r)*LDW + t*BK + cc*8);
        }
        CP_COMMIT();
    };

    float c[4][4][4];
    #pragma unroll
    for (int i=0;i<4;i++)
      #pragma unroll
      for (int j=0;j<4;j++){ c[i][j][0]=0.f;c[i][j][1]=0.f;c[i][j][2]=0.f;c[i][j][3]=0.f; }

    CPAB(0, 0);
    CPAB(1, 1);
    CP_WAIT(1);
    __syncthreads();

    int sw = 2, sr = 0;
    for (int i = 0; i < KT; i++){
        if (i + 2 < KT) CPAB(i+2, sw);

        const uint32_t sA = smBase + (uint32_t)(sr*STG_H)*2u;
        const uint32_t sB = sA + (uint32_t)A_H*2u;
        #pragma unroll
        for (int ks = 0; ks < BK/16; ks++){          // 2 k-steps of 16
            const int kb = ks*32;                    // byte advance
            uint32_t af[4][4], bfr[4][2];
            #pragma unroll
            for (int mi = 0; mi < 4; mi++)
                ldsm_x4(af[mi][0], af[mi][1], af[mi][2], af[mi][3],
                        sA + (uint32_t)(aIdx0B + mi*16*80 + kb));
            #pragma unroll
            for (int ni2 = 0; ni2 < 2; ni2++)
                ldsm_x4(bfr[2*ni2][0], bfr[2*ni2][1], bfr[2*ni2+1][0], bfr[2*ni2+1][1],
                        sB + (uint32_t)(bIdx0B + ni2*16*80 + kb));
            #pragma unroll
            for (int mi = 0; mi < 4; mi++)
              #pragma unroll
              for (int ni = 0; ni < 4; ni++)
                asm volatile("mma.sync.aligned.m16n8k16.row.col.f32.f16.f16.f32 "
                  "{%0,%1,%2,%3}, {%4,%5,%6,%7}, {%8,%9}, {%0,%1,%2,%3};"
                  : "+f"(c[mi][ni][0]), "+f"(c[mi][ni][1]),
                    "+f"(c[mi][ni][2]), "+f"(c[mi][ni][3])
                  : "r"(af[mi][0]), "r"(af[mi][1]), "r"(af[mi][2]), "r"(af[mi][3]),
                    "r"(bfr[ni][0]), "r"(bfr[ni][1]));
        }
        if (i + 2 < KT){ CP_WAIT(1); } else { CP_WAIT(0); }
        __syncthreads();

        sw = (sw == 2) ? 0 : sw + 1;
        sr = (sr == 2) ? 0 : sr + 1;
    }

    const int grp2 = grp, tig2 = tig;
    if (EPI == 0){
        #pragma unroll
        for (int ni = 0; ni < 4; ni++){
            int col = n0 + wn*32 + ni*8 + tig2*2;
            float b0 = bias[col], b1v = bias[col+1];
            #pragma unroll
            for (int mi = 0; mi < 4; mi++){
                int row = m0 + wm*64 + mi*16 + grp2;
                g_P[(size_t)row*NH + col    ] = c[mi][ni][0] + b0;
                g_P[(size_t)row*NH + col + 1] = c[mi][ni][1] + b1v;
                g_P[(size_t)(row+8)*NH + col    ] = c[mi][ni][2] + b0;
                g_P[(size_t)(row+8)*NH + col + 1] = c[mi][ni][3] + b1v;
            }
        }
        __syncthreads();
        if (tid == 0){
            __threadfence();
            atomicAdd(&g_done, 1);
        }
    } else {
        if (tid == 0){
            while (*((volatile int*)&g_done) < NBLK_A) __nanosleep(64);
        }
        __syncthreads();
        __threadfence();
        #pragma unroll
        for (int mi = 0; mi < 4; mi++){
            int row = m0 + wm*64 + mi*16 + grp2;
            int ba = row / KOBJ, bb = (row + 8) / KOBJ;
            float rs0 = 0.f, rs1 = 0.f;
            #pragma unroll
            for (int ni = 0; ni < 4; ni++){
                int col = n0 + wn*32 + ni*8 + tig2*2;
                float wl0 = __ldg(Wl + col), wl1 = __ldg(Wl + col + 1);
                rs0 += fmaxf(c[mi][ni][0] + g_P[(size_t)ba*NH + col    ], 0.f) * wl0
                     + fmaxf(c[mi][ni][1] + g_P[(size_t)ba*NH + col + 1], 0.f) * wl1;
                rs1 += fmaxf(c[mi][ni][2] + g_P[(size_t)bb*NH + col    ], 0.f) * wl0
                     + fmaxf(c[mi][ni][3] + g_P[(size_t)bb*NH + col + 1], 0.f) * wl1;
            }
            rs0 += __shfl_xor_sync(0xffffffffu, rs0, 1);
            rs0 += __shfl_xor_sync(0xffffffffu, rs0, 2);
            rs1 += __shfl_xor_sync(0xffffffffu, rs1, 1);
            rs1 += __shfl_xor_sync(0xffffffffu, rs1, 2);
            if (tig2 == 0){
                atomicAdd(&g_logits[row],     rs0);
                atomicAdd(&g_logits[row + 8], rs1);
            }
        }
    }
}

// one launch: bids [0,512) = stage A (wave-1, retire fast), rest = stage B
__global__ void __launch_bounds__(THREADS, 2)
gemm_merged(const float* __restrict__ b1, const float* __restrict__ Wl)
{
    extern __shared__ __half smh[];
    const int bid = blockIdx.x;
    if (bid < NBLK_A){
        gemm_body<0>((bid & 63)*BM, (bid >> 6)*BN, g_qh, b1, nullptr, smh);
    } else {
        const int b = bid - NBLK_A;
        gemm_body<1>((b % 384)*BM, (b / 384)*BN, g_vh, nullptr, Wl, smh);
    }
}

__global__ void __launch_bounds__(256) final_kernel(
    const float* __restrict__ mask, const float* __restrict__ bl,
    const float* __restrict__ Wse1, const float* __restrict__ Wse2,
    const float* __restrict__ Wf,   const float* __restrict__ bf,
    float* __restrict__ out)
{
    int b = blockIdx.x, tid = threadIdx.x;
    __shared__ float  s_l[KOBJ], s_s[KOBJ];
    __shared__ float4 s_wf[VD/4], s_bf[VD/4];
    for (int d = tid; d < VD/4; d += 256){
        s_wf[d] = ((const float4*)Wf)[d];
        s_bf[d] = ((const float4*)bf)[d];
    }
    if (tid < KOBJ) s_l[tid] = g_logits[b*KOBJ + tid] + bl[0];
    __syncthreads();
    if (tid < KOBJ){
        float l = s_l[tid];
        float mx = s_l[0];
        #pragma unroll
        for (int k=1;k<KOBJ;k++) mx = fmaxf(mx, s_l[k]);
        float sum = 0.f;
        #pragma unroll
        for (int k=0;k<KOBJ;k++) sum += expf(s_l[k]-mx);
        out[b*KOBJ + tid] = expf(l-mx)/sum;
        float total = 0.f;
        #pragma unroll
        for (int k=0;k<KOBJ;k++) total += s_l[k]*mask[b*KOBJ+k];
        float x = total - l*mask[b*KOBJ+tid];
        float acc = 0.f;
        for (int i=0;i<128;i++) acc += Wse2[i]*fmaxf(x*Wse1[i], 0.f);
        float y = 1.f/(1.f + expf(-acc));
        s_s[tid] = x*(1.f-y) + l;
    }
    __syncthreads();
    float* out2 = out + NROWS;
    #pragma unroll
    for (int k=0;k<KOBJ;k++){
        float s = s_s[k];
        float4* o = (float4*)(out2 + (size_t)(b*KOBJ+k)*VD);
        for (int d = tid; d < VD/4; d += 256){
            float4 wf = s_wf[d], bv = s_bf[d];
            __stcs(o + d, make_float4(fmaf(s,wf.x,bv.x), fmaf(s,wf.y,bv.y),
                                      fmaf(s,wf.z,bv.z), fmaf(s,wf.w,bv.w)));
        }
    }
}

extern "C" void kernel_launch(void* const* d_in, const int* in_sizes, int n_in,
                              void* d_out, int out_size)
{
    const float* v    = (const float*)d_in[0];
    const float* q    = (const float*)d_in[1];
    const float* mask = (const float*)d_in[2];
    const float* W1   = (const float*)d_in[3];
    const float* b1   = (const float*)d_in[4];
    const float* Wl   = (const float*)d_in[5];
    const float* bl   = (const float*)d_in[6];
    const float* Wse1 = (const float*)d_in[7];
    const float* Wse2 = (const float*)d_in[8];
    const float* Wf   = (const float*)d_in[9];
    const float* bf   = (const float*)d_in[10];
    float* out = (float*)d_out;

    cudaFuncSetAttribute(gemm_merged, cudaFuncAttributeMaxDynamicSharedMemorySize, SMEM_DYN);

    zero_logits_kernel<<<(NROWS+255)/256, 256>>>();
    cvt_w_kernel<<<(NH*LDW/4)/256, 256>>>((const float4*)W1);
    cvt_q_kernel<<<((size_t)BATCH*QD/4)/256, 256>>>((const float4*)q);
    cvt_v_kernel<<<((size_t)NROWS*VD/4)/256, 256>>>((const float4*)v);
    gemm_merged<<<NBLK_A + NBLK_B, THREADS, SMEM_DYN>>>(b1, Wl);
    final_kernel<<<BATCH, 256>>>(mask, bl, Wse1, Wse2, Wf, bf, out);
}